// round 3
// baseline (speedup 1.0000x reference)
#include <cuda_runtime.h>

// VIN_68401649156499 — round 3: f32x2 Bellman loop, minimal packing overhead
//
// r = conv(input, w_eff) + b_eff   (w_eff collapses the 150-ch hidden layer)
// qr_a = conv(r, w_q[a])           (REGISTER-resident packed pairs, fused into tap 0)
// v0 = max_a qr_a
// 79x: v = max_a (qr_a + conv(v, w_w[a]))   via fma.rn.f32x2, SMEM double-buffer
// final q_a = qr_a + conv(v, w_w[a]); logits = q[b,:,sx,sy]
//
// 256 threads: thread t owns row y=t>>2, cols x0=(t&3)*16 .. x0+15 (8 pixel pairs).
// v[x] stored at plane col x+2 so aligned pairs (v[2k],v[2k+1]) are 8B-aligned LDS.64.

#define RS 68               // row stride (floats), even; 272B rows spread banks
#define PR 66               // 64 rows + 2 halo
#define PLANE (PR * RS)
#define NPIX 4096
typedef unsigned long long ull;

__device__ __forceinline__ ull pk(float lo, float hi) {
    ull r; asm("mov.b64 %0, {%1, %2};" : "=l"(r) : "f"(lo), "f"(hi)); return r;
}
__device__ __forceinline__ float2 up(ull v) {
    float2 r; asm("mov.b64 {%0, %1}, %2;" : "=f"(r.x), "=f"(r.y) : "l"(v)); return r;
}
__device__ __forceinline__ ull ffma2(ull a, ull b, ull c) {
    ull d; asm("fma.rn.f32x2 %0, %1, %2, %3;" : "=l"(d) : "l"(a), "l"(b), "l"(c)); return d;
}

__shared__ float s_plane0[PLANE];
__shared__ float s_plane1[PLANE];
__shared__ float s_weff[20];
__shared__ ull   s_ww[45];          // packed (w,w) iteration weights

// acc[a][p] = qr[a][p] + conv3x3(w_w[a], v)  for this thread's 8 pixel pairs.
__device__ __forceinline__ void bellman(ull acc[5][8], const float* __restrict__ vi,
                                        const ull qrp[5][8], int y, int x0) {
    #pragma unroll
    for (int dy = 0; dy < 3; ++dy) {
        const float* row = vi + (y + dy) * RS;
        // aligned pairs A_p = (v[x0+2p], v[x0+2p+1])  -> direct LDS.64
        ull A[8];
        #pragma unroll
        for (int p = 0; p < 8; ++p) A[p] = *(const ull*)(row + x0 + 2 + 2 * p);
        float eL = row[x0 + 1];      // v[x0-1]  (halo 0 at x0==0)
        float eR = row[x0 + 18];     // v[x0+16] (halo 0 at x0==48)
        // misaligned pairs M_p = (v[x0+2p-1], v[x0+2p]); note dx=2 pair of p is M_{p+1}
        ull M[9];
        {
            float2 u[8];
            #pragma unroll
            for (int p = 0; p < 8; ++p) u[p] = up(A[p]);
            M[0] = pk(eL, u[0].x);
            #pragma unroll
            for (int p = 1; p < 8; ++p) M[p] = pk(u[p - 1].y, u[p].x);
            M[8] = pk(u[7].y, eR);
        }
        // broadcast weight pairs for this dy row
        ull w0[5], w1[5], w2[5];
        #pragma unroll
        for (int a = 0; a < 5; ++a) {
            w0[a] = s_ww[a * 9 + dy * 3 + 0];
            w1[a] = s_ww[a * 9 + dy * 3 + 1];
            w2[a] = s_ww[a * 9 + dy * 3 + 2];
        }
        #pragma unroll
        for (int p = 0; p < 8; ++p) {
            #pragma unroll
            for (int a = 0; a < 5; ++a) {
                ull t = (dy == 0) ? ffma2(w0[a], M[p], qrp[a][p])   // fused acc init
                                  : ffma2(w0[a], M[p], acc[a][p]);
                t = ffma2(w1[a], A[p], t);
                acc[a][p] = ffma2(w2[a], M[p + 1], t);
            }
        }
    }
}

__global__ __launch_bounds__(256, 1) void vin_kernel(
    const float* __restrict__ input,   // [128,2,64,64]
    const int*   __restrict__ coords,  // [128,4]
    const float* __restrict__ w_h,     // [150,2,3,3]
    const float* __restrict__ b_h,     // [150]
    const float* __restrict__ w_r,     // [150]
    const float* __restrict__ w_q,     // [5,1,3,3]
    const float* __restrict__ w_w,     // [5,1,3,3]
    float* __restrict__ out_q,         // [128,5,64,64]
    float* __restrict__ out_logits)    // [128,5]
{
    const int b  = blockIdx.x;
    const int t  = threadIdx.x;
    const int y  = t >> 2;            // 0..63
    const int x0 = (t & 3) * 16;      // 0,16,32,48

    // ---- zero padded planes (halo must stay zero forever) ----
    for (int k = t; k < PLANE; k += 256) { s_plane0[k] = 0.f; s_plane1[k] = 0.f; }

    // ---- collapse hidden layer; pack iteration weights ----
    if (t < 18) {
        float s = 0.f;
        for (int c = 0; c < 150; ++c) s += w_r[c] * w_h[c * 18 + t];
        s_weff[t] = s;
    } else if (t == 18) {
        float s = 0.f;
        for (int c = 0; c < 150; ++c) s += w_r[c] * b_h[c];
        s_weff[18] = s;
    } else if (t >= 32 && t < 77) {
        float w = w_w[t - 32];
        s_ww[t - 32] = pk(w, w);
    }
    __syncthreads();

    // ---- stage input channels into the two planes (v[x] at col x+2, row y+1) ----
    const float* inb = input + (size_t)b * 2 * NPIX;
    #pragma unroll
    for (int k = 0; k < 32; ++k) {
        int lin = k * 256 + t;                 // 0..8191
        int rem = lin & 4095;
        float v = inb[lin];
        float* pl = (lin < 4096) ? s_plane0 : s_plane1;
        pl[((rem >> 6) + 1) * RS + (rem & 63) + 2] = v;
    }
    __syncthreads();

    // ---- r = conv(input, weff) + beff ----
    float weff[18];
    #pragma unroll
    for (int k = 0; k < 18; ++k) weff[k] = s_weff[k];
    const float beff = s_weff[18];

    float rv[16];
    #pragma unroll
    for (int i = 0; i < 16; ++i) {
        float s = beff;
        #pragma unroll
        for (int dy = 0; dy < 3; ++dy)
            #pragma unroll
            for (int dx = 0; dx < 3; ++dx) {
                int off = (y + dy) * RS + x0 + i + dx + 1;   // v[x0+i+dx-1]
                s = fmaf(weff[0 * 9 + dy * 3 + dx], s_plane0[off], s);
                s = fmaf(weff[1 * 9 + dy * 3 + dx], s_plane1[off], s);
            }
        rv[i] = s;
    }
    __syncthreads();

    // ---- r -> plane0 interior ----
    #pragma unroll
    for (int i = 0; i < 16; ++i) s_plane0[(y + 1) * RS + x0 + i + 2] = rv[i];
    __syncthreads();

    // ---- qr_a = conv(r, w_q[a]) -> packed register pairs; v0 = max_a -> plane1 ----
    float wq[45];
    #pragma unroll
    for (int k = 0; k < 45; ++k) wq[k] = w_q[k];

    ull qrp[5][8];
    #pragma unroll
    for (int p = 0; p < 8; ++p) {
        float q[5][2];
        #pragma unroll
        for (int h = 0; h < 2; ++h) {
            int i = 2 * p + h;
            #pragma unroll
            for (int a = 0; a < 5; ++a) {
                float s = 0.f;
                #pragma unroll
                for (int dy = 0; dy < 3; ++dy)
                    #pragma unroll
                    for (int dx = 0; dx < 3; ++dx)
                        s = fmaf(wq[a * 9 + dy * 3 + dx],
                                 s_plane0[(y + dy) * RS + x0 + i + dx + 1], s);
                q[a][h] = s;
            }
            float m = q[0][h];
            #pragma unroll
            for (int a = 1; a < 5; ++a) m = fmaxf(m, q[a][h]);
            s_plane1[(y + 1) * RS + x0 + i + 2] = m;
        }
        #pragma unroll
        for (int a = 0; a < 5; ++a) qrp[a][p] = pk(q[a][0], q[a][1]);
    }
    __syncthreads();

    // ---- 79 Bellman iterations (it even: plane1 -> plane0) ----
    for (int it = 0; it < 79; ++it) {
        const float* vi = (it & 1) ? s_plane0 : s_plane1;
        float*       vo = (it & 1) ? s_plane1 : s_plane0;
        ull acc[5][8];
        bellman(acc, vi, qrp, y, x0);

        float* orow = vo + (y + 1) * RS + x0 + 2;
        #pragma unroll
        for (int p = 0; p < 8; ++p) {
            float2 m = up(acc[0][p]);
            #pragma unroll
            for (int a = 1; a < 5; ++a) {
                float2 q = up(acc[a][p]);
                m.x = fmaxf(m.x, q.x);
                m.y = fmaxf(m.y, q.y);
            }
            *(float2*)(orow + 2 * p) = m;
        }
        __syncthreads();
    }

    // ---- final q from plane0 (it=78 wrote plane0) ----
    ull acc[5][8];
    bellman(acc, s_plane0, qrp, y, x0);

    const int sx = coords[b * 4 + 0];
    const int sy = coords[b * 4 + 1];
    float* oq = out_q + (size_t)b * 5 * NPIX;

    #pragma unroll
    for (int a = 0; a < 5; ++a) {
        float2 f[8];
        #pragma unroll
        for (int p = 0; p < 8; ++p) f[p] = up(acc[a][p]);
        float* base = oq + a * NPIX + y * 64 + x0;
        #pragma unroll
        for (int g = 0; g < 4; ++g)
            *reinterpret_cast<float4*>(base + 4 * g) =
                make_float4(f[2 * g].x, f[2 * g].y, f[2 * g + 1].x, f[2 * g + 1].y);
    }

    if (y == sx && sy >= x0 && sy < x0 + 16) {
        int i = sy - x0;
        #pragma unroll
        for (int a = 0; a < 5; ++a) {
            float2 f = up(acc[a][i >> 1]);
            out_logits[b * 5 + a] = (i & 1) ? f.y : f.x;
        }
    }
}

extern "C" void kernel_launch(void* const* d_in, const int* in_sizes, int n_in,
                              void* d_out, int out_size) {
    const float* input  = (const float*)d_in[0];
    const int*   coords = (const int*)  d_in[1];
    const float* w_h    = (const float*)d_in[2];
    const float* b_h    = (const float*)d_in[3];
    const float* w_r    = (const float*)d_in[4];
    const float* w_q    = (const float*)d_in[5];
    const float* w_w    = (const float*)d_in[6];
    float* out = (float*)d_out;

    vin_kernel<<<128, 256>>>(input, coords, w_h, b_h, w_r, w_q, w_w,
                             out, out + 128 * 5 * NPIX);
}

// round 4
// speedup vs baseline: 1.2070x; 1.2070x over previous
#include <cuda_runtime.h>

// VIN_68401649156499 — round 4: y-interleaved pair planes, pure-FFMA2 Bellman loop
//
// Pixel pair = (v[y][x], v[y+32][x]) stored contiguously -> every conv operand is an
// aligned LDS.64 pair; no repacking MOVs. 256 thr: warp w owns pair-cols w*8..w*8+7,
// lane l owns pair-row l (pixels rows l and l+32).

#define PS 67                 // pair stride per interleaved row (odd -> conflict-free)
#define PROWS 34              // pair rows j=0..33  (logical pair rows -1..32)
#define PPLANE (PS * PROWS)   // 2278 pairs
#define FRS 68                // flat scratch row stride (floats)
#define NPIX 4096
typedef unsigned long long ull;

__device__ __forceinline__ ull pk(float lo, float hi) {
    ull r; asm("mov.b64 %0, {%1, %2};" : "=l"(r) : "f"(lo), "f"(hi)); return r;
}
__device__ __forceinline__ float2 up(ull v) {
    float2 r; asm("mov.b64 {%0, %1}, %2;" : "=f"(r.x), "=f"(r.y) : "l"(v)); return r;
}
__device__ __forceinline__ ull ffma2(ull a, ull b, ull c) {
    ull d; asm("fma.rn.f32x2 %0, %1, %2, %3;" : "=l"(d) : "l"(a), "l"(b), "l"(c)); return d;
}

// shared: P0 [0..2277], P1 [2278..4555], ww pairs [4556..4600], weff floats after
__shared__ ull s_mem8[4612];

// acc[a][c] = qr[a][c] + conv3x3(w_w[a], v)  over this thread's 8 pair-columns
__device__ __forceinline__ void bellman(ull acc[5][8], const ull* __restrict__ vi,
                                        const ull qrp[5][8], int l, int x0) {
    const ull* s_ww = s_mem8 + 4556;
    #pragma unroll
    for (int dy = 0; dy < 3; ++dy) {
        const ull* row = vi + (l + dy) * PS + x0;   // row[k] = pair col x0-1+k
        ull L[10];
        #pragma unroll
        for (int k = 0; k < 10; ++k) L[k] = row[k];
        ull wr[15];
        #pragma unroll
        for (int a = 0; a < 5; ++a)
            #pragma unroll
            for (int dx = 0; dx < 3; ++dx)
                wr[a * 3 + dx] = s_ww[a * 9 + dy * 3 + dx];
        #pragma unroll
        for (int c = 0; c < 8; ++c) {
            #pragma unroll
            for (int a = 0; a < 5; ++a) {
                ull t = (dy == 0) ? ffma2(wr[a * 3 + 0], L[c], qrp[a][c])
                                  : ffma2(wr[a * 3 + 0], L[c], acc[a][c]);
                t = ffma2(wr[a * 3 + 1], L[c + 1], t);
                acc[a][c] = ffma2(wr[a * 3 + 2], L[c + 2], t);
            }
        }
    }
}

__global__ __launch_bounds__(256, 1) void vin_kernel(
    const float* __restrict__ input,   // [128,2,64,64]
    const int*   __restrict__ coords,  // [128,4]
    const float* __restrict__ w_h,     // [150,2,3,3]
    const float* __restrict__ b_h,     // [150]
    const float* __restrict__ w_r,     // [150]
    const float* __restrict__ w_q,     // [5,1,3,3]
    const float* __restrict__ w_w,     // [5,1,3,3]
    float* __restrict__ out_q,         // [128,5,64,64]
    float* __restrict__ out_logits)    // [128,5]
{
    const int b  = blockIdx.x;
    const int t  = threadIdx.x;
    const int l  = t & 31;            // pair row (pixels rows l and l+32)
    const int x0 = (t >> 5) * 8;      // pair cols x0..x0+7

    float* fmem  = (float*)s_mem8;     // flat view of P0+P1 region (9112 floats)
    float* flatA = fmem;               // setup scratch A (aliases P0)
    float* flatB = fmem + 2 * PPLANE;  // setup scratch B (aliases P1)
    float* sweff = (float*)(s_mem8 + 4601);

    // ---- zero P0/P1 region; build weff/beff and packed w_w pairs ----
    for (int k = t; k < 2 * PPLANE * 2; k += 256) fmem[k] = 0.f;
    if (t < 18) {
        float s = 0.f;
        for (int c = 0; c < 150; ++c) s += w_r[c] * w_h[c * 18 + t];
        sweff[t] = s;
    } else if (t == 18) {
        float s = 0.f;
        for (int c = 0; c < 150; ++c) s += w_r[c] * b_h[c];
        sweff[18] = s;
    } else if (t >= 32 && t < 77) {
        float w = w_w[t - 32];
        s_mem8[4556 + t - 32] = pk(w, w);
    }
    __syncthreads();

    // ---- stage input channels into flat scratch (pixel (y,x) at (y+1)*FRS + x+1) ----
    const float* inb = input + (size_t)b * 2 * NPIX;
    #pragma unroll
    for (int k = 0; k < 32; ++k) {
        int lin = k * 256 + t;
        int rem = lin & 4095;
        float* dst = (lin < 4096) ? flatA : flatB;
        dst[((rem >> 6) + 1) * FRS + (rem & 63) + 1] = inb[lin];
    }
    __syncthreads();

    // ---- r = conv(input, weff) + beff at this thread's 16 pixels ----
    float weff[18];
    #pragma unroll
    for (int k = 0; k < 18; ++k) weff[k] = sweff[k];
    const float beff = sweff[18];

    float rA[8], rB[8];
    #pragma unroll
    for (int c = 0; c < 8; ++c) {
        float sA = beff, sB = beff;
        #pragma unroll
        for (int dy = 0; dy < 3; ++dy)
            #pragma unroll
            for (int dx = 0; dx < 3; ++dx) {
                int oA = (l + dy) * FRS + x0 + c + dx;
                int oB = (l + 32 + dy) * FRS + x0 + c + dx;
                float w0 = weff[dy * 3 + dx], w1 = weff[9 + dy * 3 + dx];
                sA = fmaf(w0, flatA[oA], sA); sA = fmaf(w1, flatB[oA], sA);
                sB = fmaf(w0, flatA[oB], sB); sB = fmaf(w1, flatB[oB], sB);
            }
        rA[c] = sA; rB[c] = sB;
    }
    __syncthreads();

    // ---- r -> flatA ----
    #pragma unroll
    for (int c = 0; c < 8; ++c) {
        flatA[(l + 1) * FRS + x0 + c + 1]  = rA[c];
        flatA[(l + 33) * FRS + x0 + c + 1] = rB[c];
    }
    __syncthreads();

    // ---- qr = conv(r, w_q) -> packed register pairs; v0 = max_a ----
    float wq[45];
    #pragma unroll
    for (int k = 0; k < 45; ++k) wq[k] = w_q[k];

    ull  qrp[5][8];
    float v0A[8], v0B[8];
    #pragma unroll
    for (int c = 0; c < 8; ++c) {
        float qA[5], qB[5];
        #pragma unroll
        for (int a = 0; a < 5; ++a) { qA[a] = 0.f; qB[a] = 0.f; }
        #pragma unroll
        for (int dy = 0; dy < 3; ++dy)
            #pragma unroll
            for (int dx = 0; dx < 3; ++dx) {
                float fa = flatA[(l + dy) * FRS + x0 + c + dx];
                float fb = flatA[(l + 32 + dy) * FRS + x0 + c + dx];
                #pragma unroll
                for (int a = 0; a < 5; ++a) {
                    qA[a] = fmaf(wq[a * 9 + dy * 3 + dx], fa, qA[a]);
                    qB[a] = fmaf(wq[a * 9 + dy * 3 + dx], fb, qB[a]);
                }
            }
        float mA = qA[0], mB = qB[0];
        #pragma unroll
        for (int a = 1; a < 5; ++a) { mA = fmaxf(mA, qA[a]); mB = fmaxf(mB, qB[a]); }
        v0A[c] = mA; v0B[c] = mB;
        #pragma unroll
        for (int a = 0; a < 5; ++a) qrp[a][c] = pk(qA[a], qB[a]);
    }
    __syncthreads();

    // ---- re-zero planes (flat scratch is garbage now), then write v0 into P1 ----
    for (int k = t; k < 2 * PPLANE * 2; k += 256) fmem[k] = 0.f;
    __syncthreads();

    ull* P0 = s_mem8;
    ull* P1 = s_mem8 + PPLANE;
    #pragma unroll
    for (int c = 0; c < 8; ++c)
        P1[(l + 1) * PS + x0 + c + 1] = pk(v0A[c], v0B[c]);
    if (l == 31) {
        #pragma unroll
        for (int c = 0; c < 8; ++c) P1[x0 + c + 1] = pk(0.f, v0A[c]);          // j=0: (0, v[31])
    }
    if (l == 0) {
        #pragma unroll
        for (int c = 0; c < 8; ++c) P1[33 * PS + x0 + c + 1] = pk(v0B[c], 0.f); // j=33: (v[32], 0)
    }
    __syncthreads();

    // ---- 79 Bellman iterations (even it: P1 -> P0) ----
    for (int it = 0; it < 79; ++it) {
        const ull* vi = (it & 1) ? P0 : P1;
        ull*       vo = (it & 1) ? P1 : P0;
        ull acc[5][8];
        bellman(acc, vi, qrp, l, x0);

        float mA[8], mB[8];
        #pragma unroll
        for (int c = 0; c < 8; ++c) {
            float2 m = up(acc[0][c]);
            #pragma unroll
            for (int a = 1; a < 5; ++a) {
                float2 q = up(acc[a][c]);
                m.x = fmaxf(m.x, q.x);
                m.y = fmaxf(m.y, q.y);
            }
            mA[c] = m.x; mB[c] = m.y;
            vo[(l + 1) * PS + x0 + c + 1] = pk(m.x, m.y);
        }
        if (l == 31) {
            #pragma unroll
            for (int c = 0; c < 8; ++c) vo[x0 + c + 1] = pk(0.f, mA[c]);
        }
        if (l == 0) {
            #pragma unroll
            for (int c = 0; c < 8; ++c) vo[33 * PS + x0 + c + 1] = pk(mB[c], 0.f);
        }
        __syncthreads();
    }

    // ---- final q from P0 ----
    ull acc[5][8];
    bellman(acc, P0, qrp, l, x0);

    const int sx = coords[b * 4 + 0];
    const int sy = coords[b * 4 + 1];
    float* oq = out_q + (size_t)b * 5 * NPIX;

    #pragma unroll
    for (int a = 0; a < 5; ++a) {
        float2 f[8];
        #pragma unroll
        for (int c = 0; c < 8; ++c) f[c] = up(acc[a][c]);
        float* baseA = oq + a * NPIX + l * 64 + x0;
        float* baseB = oq + a * NPIX + (l + 32) * 64 + x0;
        *reinterpret_cast<float4*>(baseA)     = make_float4(f[0].x, f[1].x, f[2].x, f[3].x);
        *reinterpret_cast<float4*>(baseA + 4) = make_float4(f[4].x, f[5].x, f[6].x, f[7].x);
        *reinterpret_cast<float4*>(baseB)     = make_float4(f[0].y, f[1].y, f[2].y, f[3].y);
        *reinterpret_cast<float4*>(baseB + 4) = make_float4(f[4].y, f[5].y, f[6].y, f[7].y);
        if (sy >= x0 && sy < x0 + 8) {
            if (sx == l)      out_logits[b * 5 + a] = f[sy - x0].x;
            if (sx == l + 32) out_logits[b * 5 + a] = f[sy - x0].y;
        }
    }
}

extern "C" void kernel_launch(void* const* d_in, const int* in_sizes, int n_in,
                              void* d_out, int out_size) {
    const float* input  = (const float*)d_in[0];
    const int*   coords = (const int*)  d_in[1];
    const float* w_h    = (const float*)d_in[2];
    const float* b_h    = (const float*)d_in[3];
    const float* w_r    = (const float*)d_in[4];
    const float* w_q    = (const float*)d_in[5];
    const float* w_w    = (const float*)d_in[6];
    float* out = (float*)d_out;

    vin_kernel<<<128, 256>>>(input, coords, w_h, b_h, w_r, w_q, w_w,
                             out, out + 128 * 5 * NPIX);
}